// round 5
// baseline (speedup 1.0000x reference)
#include <cuda_runtime.h>
#include <cuda_bf16.h>

#define BATCH       32768
#define IN_CH       512
#define OUT_CH      1024
#define NP          17
#define NSTEPS      3

#define THREADS     256
#define C4N         (IN_CH / 4)      // 128 channel-quads per row
#define ROWS_PER_T  8                // batch rows per thread
#define ROWS_PER_B  (2 * ROWS_PER_T) // 2 row-groups per block (tx>>7)
#define GRID        (BATCH / ROWS_PER_B)   // 2048 blocks

__device__ __forceinline__ float f_tanh(float x){ float r; asm("tanh.approx.f32 %0,%1;" : "=f"(r) : "f"(x)); return r; }
__device__ __forceinline__ float f_sin (float x){ float r; asm("sin.approx.f32 %0,%1;"  : "=f"(r) : "f"(x)); return r; }
__device__ __forceinline__ float f_cos (float x){ float r; asm("cos.approx.f32 %0,%1;"  : "=f"(r) : "f"(x)); return r; }

#define MAGIC 12582912.0f   // 2^23 + 2^22

struct __align__(8) F2 { float a, b; };

__global__ void __launch_bounds__(THREADS)
macunit_kernel(const float4* __restrict__ data,
               const float*  __restrict__ angles,
               const float*  __restrict__ velocity,
               const float*  __restrict__ attention,
               const float*  __restrict__ coeff,
               const float*  __restrict__ bias,
               float4*       __restrict__ out)
{
    // Extended knot table over m = floor(index)+8 in [0,17]:
    //   bgn_w = m<=7 ? m+9 : m-8 ; end_w = m<=6 ? m+10 : m-7
    // Layout: 24B stride, two 8B pairs {v0,dv} @ +0 and {a0,da} @ +8.
    // LDS.64 banks (6m,6m+1) mod 32: only m vs m+16 can collide (rare tails).
    __shared__ F2 sT[18 * 3];
    if (threadIdx.x < 18) {
        int m  = threadIdx.x;
        int bw = (m <= 7) ? m + 9  : m - 8;
        int ew = (m <= 6) ? m + 10 : m - 7;
        float v0 = velocity[bw], v1 = velocity[ew];
        float a0 = angles[bw],   a1 = angles[ew];
        sT[m * 3 + 0] = F2{ v0, v1 - v0 };
        sT[m * 3 + 1] = F2{ a0, a1 - a0 };
    }
    __syncthreads();

    const float cf = __ldg(coeff);
    const float bs = __ldg(bias);

    int tx  = threadIdx.x;
    int c4  = tx & (C4N - 1);                 // fixed channel-quad for this thread
    int sub = tx >> 7;                        // 0/1: which row-group in block
    int b0  = blockIdx.x * ROWS_PER_B + sub * ROWS_PER_T;

    // attention for channels 8*c4 .. 8*c4+7, loaded ONCE
    const float4* att4 = (const float4*)attention;
    float4 A0 = __ldg(&att4[2 * c4]);
    float4 A1 = __ldg(&att4[2 * c4 + 1]);

    #pragma unroll
    for (int g = 0; g < ROWS_PER_T; ++g) {
        int row = b0 + g;
        float4 d4 = __ldg(&data[row * C4N + c4]);
        float v[4] = {d4.x, d4.y, d4.z, d4.w};

        #pragma unroll
        for (int lane = 0; lane < 4; ++lane) {
            float d = v[lane];
            #pragma unroll
            for (int s = 0; s < NSTEPS; ++s) {
                float t  = f_tanh(fmaf(d, cf, bs));
                float w  = fmaf(t, 8.5f, 8.5f);          // index+7.5 in [0,17]
                float zb = w + MAGIC;
                int   m  = __float_as_int(zb) & 0xFF;    // round(w) in [0,17]
                float fm = zb - MAGIC;
                float pos = (w - fm) + 0.5f;             // frac(index+8)
                F2 tv = sT[m * 3 + 0];                   // {v0, dv}
                F2 ta = sT[m * 3 + 1];                   // {a0, da}
                float velo = fmaf(pos, tv.b, tv.a);
                float ang  = fmaf(pos, ta.b, ta.a);
                float sn = f_sin(ang);
                float cs = f_cos(ang);
                float st = fmaf(d, velo * sn, velo * cs);
                d = fmaf(st, 0.33333333333333333f, d);
            }
            v[lane] = d;
        }

        float4 o0 = make_float4(A0.x * v[0], A0.y * v[0], A0.z * v[1], A0.w * v[1]);
        float4 o1 = make_float4(A1.x * v[2], A1.y * v[2], A1.z * v[3], A1.w * v[3]);

        int base = row * (OUT_CH / 4) + 2 * c4;
        out[base]     = o0;
        out[base + 1] = o1;
    }
}

extern "C" void kernel_launch(void* const* d_in, const int* in_sizes, int n_in,
                              void* d_out, int out_size)
{
    const float4* data      = (const float4*)d_in[0];
    const float*  angles    = (const float*)d_in[1];
    const float*  velocity  = (const float*)d_in[2];
    const float*  attention = (const float*)d_in[3];
    const float*  coeff     = (const float*)d_in[4];
    const float*  bias      = (const float*)d_in[5];
    float4*       out       = (float4*)d_out;

    macunit_kernel<<<GRID, THREADS>>>(data, angles, velocity, attention,
                                      coeff, bias, out);
}

// round 6
// speedup vs baseline: 1.0712x; 1.0712x over previous
#include <cuda_runtime.h>
#include <cuda_bf16.h>

#define BATCH       32768
#define IN_CH       512
#define OUT_CH      1024
#define NP          17
#define NSTEPS      3

#define TOTAL4      (BATCH * IN_CH / 4)     // 4,194,304 threads
#define THREADS     256
#define FULLMASK    0xFFFFFFFFu

__device__ __forceinline__ float f_tanh(float x){ float r; asm("tanh.approx.f32 %0,%1;" : "=f"(r) : "f"(x)); return r; }
__device__ __forceinline__ float f_sin (float x){ float r; asm("sin.approx.f32 %0,%1;"  : "=f"(r) : "f"(x)); return r; }
__device__ __forceinline__ float f_cos (float x){ float r; asm("cos.approx.f32 %0,%1;"  : "=f"(r) : "f"(x)); return r; }

#define MAGIC 12582912.0f   // 2^23 + 2^22

__global__ void __launch_bounds__(THREADS)
macunit_kernel(const float4* __restrict__ data,
               const float*  __restrict__ angles,
               const float*  __restrict__ velocity,
               const float*  __restrict__ attention,
               const float*  __restrict__ coeff,
               const float*  __restrict__ bias,
               float4*       __restrict__ out)
{
    // Warp-register knot table: lane L holds entry L (m = floor(index)+8 in [0,17]):
    //   bgn_w = m<=7 ? m+9 : m-8 ; end_w = m<=6 ? m+10 : m-7  (torch wrap folded in)
    // Lookup via 4x SHFL.IDX — zero shared-memory traffic.
    int lane = threadIdx.x & 31;
    int m0   = (lane < 18) ? lane : 17;       // lanes 18..31 hold a harmless copy
    int bw   = (m0 <= 7) ? m0 + 9  : m0 - 8;
    int ew   = (m0 <= 6) ? m0 + 10 : m0 - 7;
    float rv0 = __ldg(&velocity[bw]);
    float rdv = __ldg(&velocity[ew]) - rv0;
    float ra0 = __ldg(&angles[bw]);
    float rda = __ldg(&angles[ew]) - ra0;

    const float cf = __ldg(coeff);
    const float bs = __ldg(bias);

    int idx = blockIdx.x * THREADS + threadIdx.x;   // grid covers TOTAL4 exactly

    float4 d4 = __ldg(&data[idx]);
    float v[4] = {d4.x, d4.y, d4.z, d4.w};

    #pragma unroll
    for (int ln = 0; ln < 4; ++ln) {
        float d = v[ln];
        #pragma unroll
        for (int s = 0; s < NSTEPS; ++s) {
            float t  = f_tanh(fmaf(d, cf, bs));
            float w  = fmaf(t, 8.5f, 8.5f);          // index+7.5 in [0,17]
            float zb = w + MAGIC;
            int   m  = __float_as_int(zb) & 0xFF;    // round(w) = floor(index+8)
            float fm = zb - MAGIC;
            float pos = (w - fm) + 0.5f;             // frac(index+8)
            float v0 = __shfl_sync(FULLMASK, rv0, m);
            float dv = __shfl_sync(FULLMASK, rdv, m);
            float a0 = __shfl_sync(FULLMASK, ra0, m);
            float da = __shfl_sync(FULLMASK, rda, m);
            float velo = fmaf(pos, dv, v0);
            float ang  = fmaf(pos, da, a0);
            float sn = f_sin(ang);
            float cs = f_cos(ang);
            float st = fmaf(d, velo * sn, velo * cs);  // velo*cos + d*velo*sin
            d = fmaf(st, 0.33333333333333333f, d);
        }
        v[ln] = d;
    }

    int c4 = idx & (IN_CH / 4 - 1);          // channel-quad within row
    int b  = idx >> 7;                       // batch row

    const float4* att4 = (const float4*)attention;
    float4 A0 = __ldg(&att4[2 * c4]);
    float4 A1 = __ldg(&att4[2 * c4 + 1]);

    float4 o0 = make_float4(A0.x * v[0], A0.y * v[0], A0.z * v[1], A0.w * v[1]);
    float4 o1 = make_float4(A1.x * v[2], A1.y * v[2], A1.z * v[3], A1.w * v[3]);

    int base = b * (OUT_CH / 4) + 2 * c4;
    out[base]     = o0;
    out[base + 1] = o1;
}

extern "C" void kernel_launch(void* const* d_in, const int* in_sizes, int n_in,
                              void* d_out, int out_size)
{
    const float4* data      = (const float4*)d_in[0];
    const float*  angles    = (const float*)d_in[1];
    const float*  velocity  = (const float*)d_in[2];
    const float*  attention = (const float*)d_in[3];
    const float*  coeff     = (const float*)d_in[4];
    const float*  bias      = (const float*)d_in[5];
    float4*       out       = (float4*)d_out;

    dim3 grid(TOTAL4 / THREADS);
    macunit_kernel<<<grid, THREADS>>>(data, angles, velocity, attention,
                                      coeff, bias, out);
}

// round 9
// speedup vs baseline: 1.1626x; 1.0853x over previous
#include <cuda_runtime.h>
#include <cuda_bf16.h>
#include <math.h>

#define BATCH       32768
#define IN_CH       512
#define OUT_CH      1024
#define NP          17
#define NSTEPS      3

#define TOTAL4      (BATCH * IN_CH / 4)     // 4,194,304 element-quads
#define MAIN_THREADS 1024
#define MAIN_BLOCKS  296                    // 2 per SM (148 SMs)
#define STRIDE      (MAIN_BLOCKS * MAIN_THREADS)

#define N_TAB       16384
#define TAB_LO      (-8.0f)
#define TAB_HI      ( 8.0f)
#define TAB_SCALE   ((float)N_TAB / (TAB_HI - TAB_LO))   // 1024.0f
#define SMEM_BYTES  ((N_TAB + 4) * (int)sizeof(float))   // 65552

#define MAGIC 12582912.0f   // 2^23 + 2^22

__device__ __align__(16) float g_tab[N_TAB + 4];   // y at 16385 nodes (+pad)

// ---------------- builder: accurate evaluation of composed F at nodes --------
__device__ __forceinline__ float F_exact(float d, float cf, float bs,
                                         const float* __restrict__ angles,
                                         const float* __restrict__ velocity)
{
    #pragma unroll
    for (int s = 0; s < NSTEPS; ++s) {
        float t     = tanhf(fmaf(d, cf, bs));
        float index = fmaf(t, 0.5f * (float)NP, 1.0f);   // in [-7.5, 9.5]
        float fb    = floorf(index);
        int   bgn   = (int)fb;
        int   end   = bgn + 1;                            // end<NP always
        float pos = index - fb;
        int bw = (bgn < 0) ? bgn + NP : bgn;
        int ew = (end < 0) ? end + NP : end;
        float velo = (1.0f - pos) * velocity[bw] + pos * velocity[ew];
        float ang  = (1.0f - pos) * angles[bw]   + pos * angles[ew];
        float sn = sinf(ang), cs = cosf(ang);
        float st = fmaf(d, velo * sn, velo * cs);
        d = fmaf(st, 1.0f / (float)NSTEPS, d);
    }
    return d;
}

__global__ void build_tab_kernel(const float* __restrict__ angles,
                                 const float* __restrict__ velocity,
                                 const float* __restrict__ coeff,
                                 const float* __restrict__ bias)
{
    int i = blockIdx.x * 256 + threadIdx.x;       // 0 .. 16639
    if (i > N_TAB) return;                         // need nodes 0..16384
    float cf = __ldg(coeff), bs = __ldg(bias);
    float d = TAB_LO + (float)i * ((TAB_HI - TAB_LO) / (float)N_TAB);
    g_tab[i] = F_exact(d, cf, bs, angles, velocity);
}

// ---------------- main: two smem loads per element ---------------------------
__global__ void __launch_bounds__(MAIN_THREADS)
macunit_main(const float4* __restrict__ data,
             const float*  __restrict__ attention,
             float4*       __restrict__ out)
{
    extern __shared__ float sY[];
    // stage 16384 floats = 4096 float4 = exactly 4 iters x 1024 threads
    {
        const float4* gt  = (const float4*)g_tab;
        float4*       st4 = (float4*)sY;
        #pragma unroll
        for (int i = 0; i < 4; ++i)
            st4[threadIdx.x + i * MAIN_THREADS] = gt[threadIdx.x + i * MAIN_THREADS];
        if (threadIdx.x == 0) sY[N_TAB] = g_tab[N_TAB];   // tail node
    }
    __syncthreads();

    int tid = blockIdx.x * MAIN_THREADS + threadIdx.x;
    int c4  = tid & (IN_CH / 4 - 1);     // invariant across grid-stride iters
    const float4* att4 = (const float4*)attention;
    float4 A0 = __ldg(&att4[2 * c4]);
    float4 A1 = __ldg(&att4[2 * c4 + 1]);

    for (int idx = tid; idx < TOTAL4; idx += STRIDE) {
        float4 d4 = __ldg(&data[idx]);
        float v[4] = {d4.x, d4.y, d4.z, d4.w};
        float r[4];

        #pragma unroll
        for (int ln = 0; ln < 4; ++ln) {
            float u = fmaf(v[ln], TAB_SCALE, -TAB_LO * TAB_SCALE); // (d+8)*1024
            u = fminf(fmaxf(u, 0.0f), (float)N_TAB - 1.0f);
            float w  = u - 0.5f;
            float zb = w + MAGIC;                     // RN -> round(w)=floor(u)
            int   m  = __float_as_int(zb) & (N_TAB - 1);
            float fm = zb - MAGIC;
            float pos = (w - fm) + 0.5f;              // u - floor(u)
            float y0 = sY[m];
            float y1 = sY[m + 1];
            r[ln] = fmaf(pos, y1 - y0, y0);           // F(d)
        }

        float4 o0 = make_float4(A0.x * r[0], A0.y * r[0], A0.z * r[1], A0.w * r[1]);
        float4 o1 = make_float4(A1.x * r[2], A1.y * r[2], A1.z * r[3], A1.w * r[3]);

        int b    = idx >> 7;
        int base = b * (OUT_CH / 4) + 2 * c4;
        out[base]     = o0;
        out[base + 1] = o1;
    }
}

extern "C" void kernel_launch(void* const* d_in, const int* in_sizes, int n_in,
                              void* d_out, int out_size)
{
    const float4* data      = (const float4*)d_in[0];
    const float*  angles    = (const float*)d_in[1];
    const float*  velocity  = (const float*)d_in[2];
    const float*  attention = (const float*)d_in[3];
    const float*  coeff     = (const float*)d_in[4];
    const float*  bias      = (const float*)d_in[5];
    float4*       out       = (float4*)d_out;

    cudaFuncSetAttribute(macunit_main,
                         cudaFuncAttributeMaxDynamicSharedMemorySize, SMEM_BYTES);

    build_tab_kernel<<<(N_TAB + 256) / 256, 256>>>(angles, velocity, coeff, bias);
    macunit_main<<<MAIN_BLOCKS, MAIN_THREADS, SMEM_BYTES>>>(data, attention, out);
}